// round 16
// baseline (speedup 1.0000x reference)
#include <cuda_runtime.h>

#define NB 262144
#define NTHREADS (NB / 2)   // each thread: 2 elements
#define BLOCK 128

typedef unsigned long long u64;

struct CW {
    ulonglong2 W1[32][4];    // [k][j2]: 4 feature-pairs per 16B
    ulonglong2 W2T[16][8];   // [k2][jq]: k-pair-transposed W2; u64 j = (W2[2k2][j], W2[2k2+1][j])
    u64 wqb[32];             // (W1[0][k], b1[k]) — pairs with input (q, 1)
    u64 b2p[16];             // (b2[j], 0) — h2 accumulator init
    float W3f[16];
    float b3;
    float qp[7];             // q_params (only 1..6 used)
};

__constant__ CW cw;
__device__ CW d_stage;

__device__ __forceinline__ u64 pack2(float lo, float hi) {
    u64 r; asm("mov.b64 %0, {%1,%2};" : "=l"(r) : "f"(lo), "f"(hi)); return r;
}
__device__ __forceinline__ void unpack2(u64 v, float& lo, float& hi) {
    asm("mov.b64 {%0,%1}, %2;" : "=f"(lo), "=f"(hi) : "l"(v));
}
__device__ __forceinline__ u64 fma2(u64 a, u64 b, u64 c) {
    u64 r; asm("fma.rn.f32x2 %0, %1, %2, %3;" : "=l"(r) : "l"(a), "l"(b), "l"(c)); return r;
}
__device__ __forceinline__ u64 mul2(u64 a, u64 b) {
    u64 r; asm("mul.rn.f32x2 %0, %1, %2;" : "=l"(r) : "l"(a), "l"(b)); return r;
}
__device__ __forceinline__ u64 add2(u64 a, u64 b) {
    u64 r; asm("add.rn.f32x2 %0, %1, %2;" : "=l"(r) : "l"(a), "l"(b)); return r;
}

__global__ void prep_kernel(const float* __restrict__ W1, const float* __restrict__ b1,
                            const float* __restrict__ W2, const float* __restrict__ b2,
                            const float* __restrict__ W3, const float* __restrict__ b3,
                            const float* __restrict__ qp)
{
    const int tid = threadIdx.x;
    for (int i = tid; i < 32 * 4; i += blockDim.x) {
        int k = i / 4, j2 = i % 4;
        ulonglong2 a;
        a.x = pack2(W1[(1 + 4 * j2) * 32 + k], W1[(2 + 4 * j2) * 32 + k]);
        a.y = pack2(W1[(3 + 4 * j2) * 32 + k], W1[(4 + 4 * j2) * 32 + k]);
        d_stage.W1[k][j2] = a;
    }
    for (int i = tid; i < 16 * 8; i += blockDim.x) {
        int k2 = i / 8, jq = i % 8;
        ulonglong2 b;
        b.x = pack2(W2[(2 * k2) * 16 + 2 * jq],     W2[(2 * k2 + 1) * 16 + 2 * jq]);
        b.y = pack2(W2[(2 * k2) * 16 + 2 * jq + 1], W2[(2 * k2 + 1) * 16 + 2 * jq + 1]);
        d_stage.W2T[k2][jq] = b;
    }
    if (tid < 32) d_stage.wqb[tid] = pack2(W1[tid], b1[tid]);
    if (tid < 16) {
        d_stage.b2p[tid] = pack2(b2[tid], 0.0f);
        d_stage.W3f[tid] = W3[tid];
    }
    if (tid < 7) d_stage.qp[tid] = qp[tid];
    if (tid == 0) d_stage.b3 = b3[0];
}

__device__ __forceinline__ float dot17(const u64* in, const ulonglong2* w1, u64 wqb)
{
    // Two independent chains (even/odd features), merged once: depth 5.
    u64 accA = mul2(in[0], w1[0].x);
    u64 accB = mul2(in[1], w1[0].y);
    accA = fma2(in[2], w1[1].x, accA);
    accB = fma2(in[3], w1[1].y, accB);
    accA = fma2(in[4], w1[2].x, accA);
    accB = fma2(in[5], w1[2].y, accB);
    accA = fma2(in[6], w1[3].x, accA);
    accB = fma2(in[7], w1[3].y, accB);
    accA = fma2(in[8], wqb, accA);       // q*W1q + 1*b1 folded in
    u64 acc = add2(accA, accB);
    float lo, hi;
    unpack2(acc, lo, hi);
    return fmaxf(lo + hi, 0.0f);
}

__global__ __launch_bounds__(BLOCK, 4)   // 128-reg cap, 16 warps/SM
void hybridq_kernel(const float* __restrict__ xq, const float* __restrict__ xc,
                    float* __restrict__ out)
{
    const int t = blockIdx.x * BLOCK + threadIdx.x;

    // ---- Quantum feature: <Z0> = prod_{i=1..6} cos(x_q[i] + qp[i]) ----
    // (CNOT-ring GF(2): qubit-0 output = parity(b1..b6); per-qubit factor
    //  cos^2(h)-sin^2(h) = cos(2h) = cos(x+w); qubit 0's own angle cancels.)
    float q0 = 1.0f, q1 = 1.0f;
#pragma unroll
    for (int i = 1; i < 7; i++) {
        float w = cw.qp[i];
        q0 *= __cosf(__ldg(xq + (size_t)t * 7 + i) + w);
        q1 *= __cosf(__ldg(xq + ((size_t)t + NTHREADS) * 7 + i) + w);
    }

    // ---- Inputs: 8 native xc pairs + (q, 1) pair (bias folded as feature) ----
    u64 in[2][9];
    in[0][8] = pack2(q0, 1.0f);
    in[1][8] = pack2(q1, 1.0f);
    {
        const ulonglong2* c0 = (const ulonglong2*)(xc + (size_t)t * 16);
        const ulonglong2* c1 = (const ulonglong2*)(xc + ((size_t)t + NTHREADS) * 16);
#pragma unroll
        for (int p = 0; p < 4; p++) {
            ulonglong2 a = c0[p]; in[0][2 * p] = a.x; in[0][2 * p + 1] = a.y;
            ulonglong2 b = c1[p]; in[1][2 * p] = b.x; in[1][2 * p + 1] = b.y;
        }
    }

    // ---- h2 accumulators: k-pair partial sums, 16 per element ----
    // lane.lo accumulates even-k contributions, lane.hi odd-k; summed at end.
    u64 h2[2][16];
#pragma unroll
    for (int e = 0; e < 2; e++)
#pragma unroll
        for (int j = 0; j < 16; j++)
            h2[e][j] = cw.b2p[j];

    // ---- Fused layers 1+2, k processed in pairs ----
#pragma unroll 2
    for (int k2 = 0; k2 < 16; k2++) {
        ulonglong2 w1a[4], w1b[4];
#pragma unroll
        for (int p = 0; p < 4; p++) {
            w1a[p] = cw.W1[2 * k2][p];
            w1b[p] = cw.W1[2 * k2 + 1][p];
        }
        u64 wqa = cw.wqb[2 * k2];
        u64 wqb_ = cw.wqb[2 * k2 + 1];

        u64 sp[2];
#pragma unroll
        for (int e = 0; e < 2; e++) {
            float s0 = dot17(in[e], w1a, wqa);
            float s1 = dot17(in[e], w1b, wqb_);
            sp[e] = pack2(s0, s1);             // (s_even, s_odd)
        }

        ulonglong2 v0 = cw.W2T[k2][0];
        ulonglong2 v1 = cw.W2T[k2][1];
        ulonglong2 v2 = cw.W2T[k2][2];
        ulonglong2 v3 = cw.W2T[k2][3];
        ulonglong2 v4 = cw.W2T[k2][4];
        ulonglong2 v5 = cw.W2T[k2][5];
        ulonglong2 v6 = cw.W2T[k2][6];
        ulonglong2 v7 = cw.W2T[k2][7];
#pragma unroll
        for (int e = 0; e < 2; e++) {
            h2[e][0]  = fma2(sp[e], v0.x, h2[e][0]);
            h2[e][1]  = fma2(sp[e], v0.y, h2[e][1]);
            h2[e][2]  = fma2(sp[e], v1.x, h2[e][2]);
            h2[e][3]  = fma2(sp[e], v1.y, h2[e][3]);
            h2[e][4]  = fma2(sp[e], v2.x, h2[e][4]);
            h2[e][5]  = fma2(sp[e], v2.y, h2[e][5]);
            h2[e][6]  = fma2(sp[e], v3.x, h2[e][6]);
            h2[e][7]  = fma2(sp[e], v3.y, h2[e][7]);
            h2[e][8]  = fma2(sp[e], v4.x, h2[e][8]);
            h2[e][9]  = fma2(sp[e], v4.y, h2[e][9]);
            h2[e][10] = fma2(sp[e], v5.x, h2[e][10]);
            h2[e][11] = fma2(sp[e], v5.y, h2[e][11]);
            h2[e][12] = fma2(sp[e], v6.x, h2[e][12]);
            h2[e][13] = fma2(sp[e], v6.y, h2[e][13]);
            h2[e][14] = fma2(sp[e], v7.x, h2[e][14]);
            h2[e][15] = fma2(sp[e], v7.y, h2[e][15]);
        }
    }

    // ---- Layer 3: h_j = relu(lo+hi); out = b3 + sum h_j * W3[j] (2 chains) ----
    const float bb = cw.b3;
#pragma unroll
    for (int e = 0; e < 2; e++) {
        float accA = 0.0f, accB = 0.0f;
#pragma unroll
        for (int j = 0; j < 16; j += 2) {
            float lo0, hi0, lo1, hi1;
            unpack2(h2[e][j], lo0, hi0);
            unpack2(h2[e][j + 1], lo1, hi1);
            accA = fmaf(fmaxf(lo0 + hi0, 0.0f), cw.W3f[j], accA);
            accB = fmaf(fmaxf(lo1 + hi1, 0.0f), cw.W3f[j + 1], accB);
        }
        out[t + e * NTHREADS] = bb + accA + accB;
    }
}

extern "C" void kernel_launch(void* const* d_in, const int* in_sizes, int n_in,
                              void* d_out, int out_size)
{
    const float* xq = (const float*)d_in[0];
    const float* xc = (const float*)d_in[1];
    const float* qp = (const float*)d_in[2];
    const float* W1 = (const float*)d_in[3];
    const float* b1 = (const float*)d_in[4];
    const float* W2 = (const float*)d_in[5];
    const float* b2 = (const float*)d_in[6];
    const float* W3 = (const float*)d_in[7];
    const float* b3 = (const float*)d_in[8];
    float* out = (float*)d_out;

    // 1. Pack weights into the staging struct (device).
    prep_kernel<<<1, 128>>>(W1, b1, W2, b2, W3, b3, qp);

    // 2. Staging -> constant bank (D2D async memcpy; graph-capturable node).
    void* stage_ptr = nullptr;
    cudaGetSymbolAddress(&stage_ptr, d_stage);
    cudaMemcpyToSymbolAsync(cw, stage_ptr, sizeof(CW), 0, cudaMemcpyDeviceToDevice, 0);

    // 3. Main kernel: k-pair layer-2 partial sums, max independent FMA chains.
    hybridq_kernel<<<NTHREADS / BLOCK, BLOCK>>>(xq, xc, out);
}